// round 1
// baseline (speedup 1.0000x reference)
#include <cuda_runtime.h>
#include <math.h>

#define B_  2
#define S_  2048
#define D_  1024
#define H_  16
#define HD_ 64
#define EPS_ 1e-6f

// Scratch (allocation-free rule: __device__ globals)
__device__ float g_qkv[B_ * S_ * 3 * D_];   // [B*S, 3D], col = which*D + h*64 + hd
__device__ float g_o[B_ * S_ * D_];         // [B*S, D],  col = h*64 + hd

// ---------------------------------------------------------------------------
// SGEMM + bias: C[M,N] = A[M,K] @ B[K,N] + bias[N]
// 128x128 tile, BK=8, 8x8 per thread (split-tile), 256 threads.
// Requires M%128==0, N%128==0, K%8==0.
// ---------------------------------------------------------------------------
__global__ __launch_bounds__(256) void sgemm_bias_kernel(
    const float* __restrict__ A, const float* __restrict__ Bm,
    const float* __restrict__ bias, float* __restrict__ C,
    int M, int N, int K)
{
    __shared__ float As[8][128];
    __shared__ float Bs[8][128];

    const int tid = threadIdx.x;
    const int tx  = tid & 15;
    const int ty  = tid >> 4;
    const int bxn = blockIdx.x * 128;
    const int bym = blockIdx.y * 128;

    const int arow = tid >> 1;
    const int acol = (tid & 1) * 4;
    const int brow = tid >> 5;
    const int bcol = (tid & 31) * 4;

    const float* Ap = A + (size_t)(bym + arow) * K + acol;
    const float* Bp = Bm + (size_t)brow * N + bxn + bcol;

    float acc[8][8];
#pragma unroll
    for (int i = 0; i < 8; ++i)
#pragma unroll
        for (int j = 0; j < 8; ++j) acc[i][j] = 0.f;

    for (int k0 = 0; k0 < K; k0 += 8) {
        float4 a4 = *(const float4*)(Ap + k0);
        float4 b4 = *(const float4*)(Bp + (size_t)k0 * N);
        __syncthreads();
        As[acol + 0][arow] = a4.x;
        As[acol + 1][arow] = a4.y;
        As[acol + 2][arow] = a4.z;
        As[acol + 3][arow] = a4.w;
        *(float4*)&Bs[brow][bcol] = b4;
        __syncthreads();
#pragma unroll
        for (int kk = 0; kk < 8; ++kk) {
            float4 a0 = *(const float4*)&As[kk][ty * 4];
            float4 a1 = *(const float4*)&As[kk][64 + ty * 4];
            float4 b0 = *(const float4*)&Bs[kk][tx * 4];
            float4 b1 = *(const float4*)&Bs[kk][64 + tx * 4];
            float ar[8] = {a0.x, a0.y, a0.z, a0.w, a1.x, a1.y, a1.z, a1.w};
            float br[8] = {b0.x, b0.y, b0.z, b0.w, b1.x, b1.y, b1.z, b1.w};
#pragma unroll
            for (int i = 0; i < 8; ++i)
#pragma unroll
                for (int j = 0; j < 8; ++j)
                    acc[i][j] = fmaf(ar[i], br[j], acc[i][j]);
        }
    }

#pragma unroll
    for (int i = 0; i < 8; ++i) {
        int r = bym + ((i < 4) ? (ty * 4 + i) : (64 + ty * 4 + (i - 4)));
        float* Crow = C + (size_t)r * N + bxn;
#pragma unroll
        for (int jh = 0; jh < 2; ++jh) {
            int c = jh * 64 + tx * 4;
            float4 bs4 = *(const float4*)(bias + bxn + c);
            float4 o;
            o.x = acc[i][jh * 4 + 0] + bs4.x;
            o.y = acc[i][jh * 4 + 1] + bs4.y;
            o.z = acc[i][jh * 4 + 2] + bs4.z;
            o.w = acc[i][jh * 4 + 3] + bs4.w;
            *(float4*)(Crow + c) = o;
        }
    }
}

// ---------------------------------------------------------------------------
// In-place RMSNorm of q and k head-vectors (64 elems) inside g_qkv.
// One warp per vector. Total vectors = B*S*H*2.
// ---------------------------------------------------------------------------
__global__ __launch_bounds__(256) void rmsnorm_kernel(
    float* __restrict__ qkv,
    const float* __restrict__ q_scale, const float* __restrict__ k_scale)
{
    int w    = (blockIdx.x * blockDim.x + threadIdx.x) >> 5;
    int lane = threadIdx.x & 31;
    if (w >= B_ * S_ * H_ * 2) return;

    int which = w & 1;          // 0 = q, 1 = k
    int rest  = w >> 1;
    int h     = rest & (H_ - 1);
    int bs    = rest >> 4;      // H_ == 16

    float* v = qkv + (size_t)bs * (3 * D_) + which * D_ + h * HD_;
    float2 x = *(float2*)(v + lane * 2);
    float ss = x.x * x.x + x.y * x.y;
#pragma unroll
    for (int off = 16; off >= 1; off >>= 1)
        ss += __shfl_xor_sync(0xffffffffu, ss, off);
    float r = rsqrtf(ss * (1.0f / HD_) + EPS_);
    const float* sc = which ? k_scale : q_scale;
    x.x *= r * sc[lane * 2];
    x.y *= r * sc[lane * 2 + 1];
    *(float2*)(v + lane * 2) = x;
}

// ---------------------------------------------------------------------------
// Flash attention: one CTA = 64-query tile of one (b,h). 256 threads,
// 16x16 thread grid, 4x4 fragment per thread. Online softmax.
// smem tiles [64][68] (pad 4 keeps float4 alignment + breaks bank conflicts).
// ---------------------------------------------------------------------------
#define AT_PAD 68
#define PV_STEP(comp, vk)                               \
    oacc[i][0] = fmaf(p.comp, vk.x, oacc[i][0]);        \
    oacc[i][1] = fmaf(p.comp, vk.y, oacc[i][1]);        \
    oacc[i][2] = fmaf(p.comp, vk.z, oacc[i][2]);        \
    oacc[i][3] = fmaf(p.comp, vk.w, oacc[i][3]);

__global__ __launch_bounds__(256) void attn_kernel(
    const float* __restrict__ qkv, float* __restrict__ o)
{
    extern __shared__ float sm[];
    float* Qs = sm;
    float* Ks = sm + 64 * AT_PAD;
    float* Vs = sm + 2 * 64 * AT_PAD;
    float* Ps = sm + 3 * 64 * AT_PAD;

    const int q0 = blockIdx.x * 64;
    const int bh = blockIdx.y;
    const int b  = bh >> 4;            // H_ == 16
    const int h  = bh & 15;
    const int tid = threadIdx.x;
    const int tx  = tid & 15;
    const int ty  = tid >> 4;

    const float* base = qkv + (size_t)b * S_ * 3 * D_ + h * HD_;

    // load Q tile (already RMS-normed)
#pragma unroll
    for (int p = 0; p < 4; ++p) {
        int r = p * 16 + ty;
        *(float4*)&Qs[r * AT_PAD + tx * 4] =
            *(const float4*)(base + (size_t)(q0 + r) * (3 * D_) + tx * 4);
    }

    float m[4], l[4], oacc[4][4];
#pragma unroll
    for (int i = 0; i < 4; ++i) {
        m[i] = -1e30f; l[i] = 0.f;
#pragma unroll
        for (int d = 0; d < 4; ++d) oacc[i][d] = 0.f;
    }

    for (int kv0 = 0; kv0 < S_; kv0 += 64) {
        // load K, V tiles
#pragma unroll
        for (int p = 0; p < 4; ++p) {
            int r = p * 16 + ty;
            const float* grow = base + (size_t)(kv0 + r) * (3 * D_);
            *(float4*)&Ks[r * AT_PAD + tx * 4] = *(const float4*)(grow + D_ + tx * 4);
            *(float4*)&Vs[r * AT_PAD + tx * 4] = *(const float4*)(grow + 2 * D_ + tx * 4);
        }
        __syncthreads();

        // S = Q K^T  (inner dim d, vectorized by 4)
        float acc[4][4];
#pragma unroll
        for (int i = 0; i < 4; ++i)
#pragma unroll
            for (int j = 0; j < 4; ++j) acc[i][j] = 0.f;

#pragma unroll
        for (int kk = 0; kk < 64; kk += 4) {
            float4 qa[4], kb[4];
#pragma unroll
            for (int i = 0; i < 4; ++i) qa[i] = *(const float4*)&Qs[(ty * 4 + i) * AT_PAD + kk];
#pragma unroll
            for (int j = 0; j < 4; ++j) kb[j] = *(const float4*)&Ks[(tx * 4 + j) * AT_PAD + kk];
#pragma unroll
            for (int i = 0; i < 4; ++i) {
                float4 q = qa[i];
#pragma unroll
                for (int j = 0; j < 4; ++j) {
                    float4 k4 = kb[j];
                    acc[i][j] = fmaf(q.x, k4.x, acc[i][j]);
                    acc[i][j] = fmaf(q.y, k4.y, acc[i][j]);
                    acc[i][j] = fmaf(q.z, k4.z, acc[i][j]);
                    acc[i][j] = fmaf(q.w, k4.w, acc[i][j]);
                }
            }
        }

        // online softmax (rows owned across tx; reduce within 16-lane group)
#pragma unroll
        for (int i = 0; i < 4; ++i) {
            float mloc = -1e30f;
#pragma unroll
            for (int j = 0; j < 4; ++j) {
                acc[i][j] *= 0.125f;           // 1/sqrt(64)
                mloc = fmaxf(mloc, acc[i][j]);
            }
#pragma unroll
            for (int off = 8; off >= 1; off >>= 1)
                mloc = fmaxf(mloc, __shfl_xor_sync(0xffffffffu, mloc, off));
            float mnew = fmaxf(m[i], mloc);
            float corr = __expf(m[i] - mnew);
            m[i] = mnew;
            float p0 = __expf(acc[i][0] - mnew);
            float p1 = __expf(acc[i][1] - mnew);
            float p2 = __expf(acc[i][2] - mnew);
            float p3 = __expf(acc[i][3] - mnew);
            float rs = p0 + p1 + p2 + p3;
#pragma unroll
            for (int off = 8; off >= 1; off >>= 1)
                rs += __shfl_xor_sync(0xffffffffu, rs, off);
            l[i] = l[i] * corr + rs;
#pragma unroll
            for (int d = 0; d < 4; ++d) oacc[i][d] *= corr;
            *(float4*)&Ps[(ty * 4 + i) * AT_PAD + tx * 4] = make_float4(p0, p1, p2, p3);
        }
        __syncthreads();

        // O += P V (inner dim j, vectorized by 4)
#pragma unroll
        for (int jj = 0; jj < 64; jj += 4) {
            float4 pa[4];
#pragma unroll
            for (int i = 0; i < 4; ++i) pa[i] = *(const float4*)&Ps[(ty * 4 + i) * AT_PAD + jj];
            float4 vb0 = *(const float4*)&Vs[(jj + 0) * AT_PAD + tx * 4];
            float4 vb1 = *(const float4*)&Vs[(jj + 1) * AT_PAD + tx * 4];
            float4 vb2 = *(const float4*)&Vs[(jj + 2) * AT_PAD + tx * 4];
            float4 vb3 = *(const float4*)&Vs[(jj + 3) * AT_PAD + tx * 4];
#pragma unroll
            for (int i = 0; i < 4; ++i) {
                float4 p = pa[i];
                PV_STEP(x, vb0)
                PV_STEP(y, vb1)
                PV_STEP(z, vb2)
                PV_STEP(w, vb3)
            }
        }
        __syncthreads();
    }

    // epilogue: normalize and store to g_o[(b*S+q)*D + h*64 + d]
#pragma unroll
    for (int i = 0; i < 4; ++i) {
        float inv = 1.0f / l[i];
        int qrow = q0 + ty * 4 + i;
        float* orow = o + (size_t)(b * S_ + qrow) * D_ + h * HD_ + tx * 4;
        *(float4*)orow = make_float4(oacc[i][0] * inv, oacc[i][1] * inv,
                                     oacc[i][2] * inv, oacc[i][3] * inv);
    }
}

// ---------------------------------------------------------------------------
extern "C" void kernel_launch(void* const* d_in, const int* in_sizes, int n_in,
                              void* d_out, int out_size)
{
    const float* x       = (const float*)d_in[0];
    const float* Wqkv    = (const float*)d_in[1];
    const float* bqkv    = (const float*)d_in[2];
    const float* Wout    = (const float*)d_in[3];
    const float* bout    = (const float*)d_in[4];
    const float* q_scale = (const float*)d_in[5];
    const float* k_scale = (const float*)d_in[6];
    float* out = (float*)d_out;

    float* qkv; cudaGetSymbolAddress((void**)&qkv, g_qkv);
    float* o;   cudaGetSymbolAddress((void**)&o,   g_o);

    // 1) QKV projection: [4096,1024]@[1024,3072]+b
    {
        dim3 grid(3 * D_ / 128, (B_ * S_) / 128);
        sgemm_bias_kernel<<<grid, 256>>>(x, Wqkv, bqkv, qkv, B_ * S_, 3 * D_, D_);
    }

    // 2) RMSNorm q,k in place
    {
        int warps = B_ * S_ * H_ * 2;
        int blocks = (warps * 32) / 256;
        rmsnorm_kernel<<<blocks, 256>>>(qkv, q_scale, k_scale);
    }

    // 3) attention
    {
        const int smem = 4 * 64 * AT_PAD * sizeof(float);  // 69632
        cudaFuncSetAttribute((const void*)attn_kernel,
                             cudaFuncAttributeMaxDynamicSharedMemorySize, smem);
        dim3 grid(S_ / 64, B_ * H_);
        attn_kernel<<<grid, 256, smem>>>(qkv, o);
    }

    // 4) output projection: [4096,1024]@[1024,1024]+b
    {
        dim3 grid(D_ / 128, (B_ * S_) / 128);
        sgemm_bias_kernel<<<grid, 256>>>(o, Wout, bout, out, B_ * S_, D_, D_);
    }
}

// round 2
// speedup vs baseline: 4.1154x; 4.1154x over previous
#include <cuda_runtime.h>
#include <math.h>

#define B_  2
#define S_  2048
#define D_  1024
#define H_  16
#define HD_ 64
#define EPS_ 1e-6f

// fold (1/sqrt(hd)) * log2(e) into q during rmsnorm -> softmax in exp2 domain
#define QFOLD 0.18033688011112042f   // 0.125 * 1.4426950408889634

// Scratch (allocation-free rule: __device__ globals)
__device__ float g_qkv[B_ * S_ * 3 * D_];   // [B*S, 3D]
__device__ float g_o[B_ * S_ * D_];         // [B*S, D]

__device__ __forceinline__ unsigned f2tf(float x) {
    unsigned r;
    asm("cvt.rna.tf32.f32 %0, %1;" : "=r"(r) : "f"(x));
    return r;
}

__device__ __forceinline__ void mma_tf32(float* c, const unsigned* a, const unsigned* b) {
    asm volatile(
        "mma.sync.aligned.m16n8k8.row.col.f32.tf32.tf32.f32 "
        "{%0,%1,%2,%3}, {%4,%5,%6,%7}, {%8,%9}, {%0,%1,%2,%3};"
        : "+f"(c[0]), "+f"(c[1]), "+f"(c[2]), "+f"(c[3])
        : "r"(a[0]), "r"(a[1]), "r"(a[2]), "r"(a[3]), "r"(b[0]), "r"(b[1]));
}

// ---------------------------------------------------------------------------
// TF32 tensor-core GEMM + bias: C[M,N] = A[M,K] @ B[K,N] + bias[N]
// 128x128x32 tile, 256 threads (8 warps, 4x2), warp tile 32x64, m16n8k8.
// ---------------------------------------------------------------------------
#define AS_STR 36
#define BS_STR 136

__global__ __launch_bounds__(256) void gemm_tf32_kernel(
    const float* __restrict__ A, const float* __restrict__ Bm,
    const float* __restrict__ bias, float* __restrict__ C,
    int M, int N, int K)
{
    __shared__ unsigned As[128 * AS_STR];
    __shared__ unsigned Bs[32 * BS_STR];

    const int tid = threadIdx.x;
    const int wid = tid >> 5;
    const int lane = tid & 31;
    const int g = lane >> 2;      // group (row within fragment)
    const int q = lane & 3;       // thread-in-group (k/col selector)
    const int wm = wid >> 1;      // 0..3 -> m offset wm*32
    const int wn = wid & 1;       // 0..1 -> n offset wn*64
    const int bxn = blockIdx.x * 128;
    const int bym = blockIdx.y * 128;

    // global load mapping
    int ar[4], ac[4], br[4], bc[4];
    const float* Ag[4];
    const float* Bg[4];
#pragma unroll
    for (int i = 0; i < 4; ++i) {
        int idx = tid + 256 * i;
        ar[i] = idx >> 3; ac[i] = idx & 7;          // A: 128 rows x 8 float4
        br[i] = idx >> 5; bc[i] = idx & 31;         // B: 32 rows x 32 float4
        Ag[i] = A + (size_t)(bym + ar[i]) * K + ac[i] * 4;
        Bg[i] = Bm + (size_t)br[i] * N + bxn + bc[i] * 4;
    }

    float acc[2][8][4];
#pragma unroll
    for (int mf = 0; mf < 2; ++mf)
#pragma unroll
        for (int nf = 0; nf < 8; ++nf)
#pragma unroll
            for (int e = 0; e < 4; ++e) acc[mf][nf][e] = 0.f;

    const int KT = K >> 5;
    for (int kt = 0; kt < KT; ++kt) {
        float4 av[4], bv[4];
#pragma unroll
        for (int i = 0; i < 4; ++i) av[i] = *(const float4*)(Ag[i] + kt * 32);
#pragma unroll
        for (int i = 0; i < 4; ++i) bv[i] = *(const float4*)(Bg[i] + (size_t)(kt * 32) * N);
        __syncthreads();
#pragma unroll
        for (int i = 0; i < 4; ++i) {
            uint4 t = make_uint4(f2tf(av[i].x), f2tf(av[i].y), f2tf(av[i].z), f2tf(av[i].w));
            *(uint4*)&As[ar[i] * AS_STR + ac[i] * 4] = t;
            uint4 u = make_uint4(f2tf(bv[i].x), f2tf(bv[i].y), f2tf(bv[i].z), f2tf(bv[i].w));
            *(uint4*)&Bs[br[i] * BS_STR + bc[i] * 4] = u;
        }
        __syncthreads();

#pragma unroll
        for (int kk = 0; kk < 4; ++kk) {
            unsigned a[2][4], b[8][2];
#pragma unroll
            for (int mf = 0; mf < 2; ++mf) {
                int ab = (wm * 32 + mf * 16 + g) * AS_STR + kk * 8 + q;
                a[mf][0] = As[ab];
                a[mf][1] = As[ab + 8 * AS_STR];
                a[mf][2] = As[ab + 4];
                a[mf][3] = As[ab + 8 * AS_STR + 4];
            }
#pragma unroll
            for (int nf = 0; nf < 8; ++nf) {
                int bb = (kk * 8 + q) * BS_STR + wn * 64 + nf * 8 + g;
                b[nf][0] = Bs[bb];
                b[nf][1] = Bs[bb + 4 * BS_STR];
            }
#pragma unroll
            for (int mf = 0; mf < 2; ++mf)
#pragma unroll
                for (int nf = 0; nf < 8; ++nf)
                    mma_tf32(acc[mf][nf], a[mf], b[nf]);
        }
    }

    // epilogue with bias
#pragma unroll
    for (int mf = 0; mf < 2; ++mf) {
        int row0 = bym + wm * 32 + mf * 16 + g;
#pragma unroll
        for (int nf = 0; nf < 8; ++nf) {
            int col = bxn + wn * 64 + nf * 8 + 2 * q;
            float2 bsv = *(const float2*)(bias + col);
            float2 o0 = make_float2(acc[mf][nf][0] + bsv.x, acc[mf][nf][1] + bsv.y);
            float2 o1 = make_float2(acc[mf][nf][2] + bsv.x, acc[mf][nf][3] + bsv.y);
            *(float2*)(C + (size_t)row0 * N + col) = o0;
            *(float2*)(C + (size_t)(row0 + 8) * N + col) = o1;
        }
    }
}

// ---------------------------------------------------------------------------
// In-place RMSNorm of q,k head-vectors. q additionally scaled by QFOLD.
// ---------------------------------------------------------------------------
__global__ __launch_bounds__(256) void rmsnorm_kernel(
    float* __restrict__ qkv,
    const float* __restrict__ q_scale, const float* __restrict__ k_scale)
{
    int w    = (blockIdx.x * blockDim.x + threadIdx.x) >> 5;
    int lane = threadIdx.x & 31;
    if (w >= B_ * S_ * H_ * 2) return;

    int which = w & 1;          // 0 = q, 1 = k
    int rest  = w >> 1;
    int h     = rest & (H_ - 1);
    int bs    = rest >> 4;

    float* v = qkv + (size_t)bs * (3 * D_) + which * D_ + h * HD_;
    float2 x = *(float2*)(v + lane * 2);
    float ss = x.x * x.x + x.y * x.y;
#pragma unroll
    for (int off = 16; off >= 1; off >>= 1)
        ss += __shfl_xor_sync(0xffffffffu, ss, off);
    float r = rsqrtf(ss * (1.0f / HD_) + EPS_);
    if (which == 0) r *= QFOLD;
    const float* sc = which ? k_scale : q_scale;
    x.x *= r * sc[lane * 2];
    x.y *= r * sc[lane * 2 + 1];
    *(float2*)(v + lane * 2) = x;
}

// ---------------------------------------------------------------------------
// TF32 tensor-core flash attention.
// CTA: 128 queries of one (b,h). 4 warps; warp = 32 query rows x full key width.
// 64-key tiles, online softmax (exp2 domain; scale folded into q).
// ---------------------------------------------------------------------------
#define QS_STR 68
#define KS_STR 68
#define VS_STR 72
#define PS_STR 68
#define OFF_K  (128 * QS_STR)
#define OFF_V  (OFF_K + 64 * KS_STR)
#define OFF_P  (OFF_V + 64 * VS_STR)
#define ATT_SMEM ((OFF_P + 128 * PS_STR) * 4)

__global__ __launch_bounds__(128) void attn_tf32_kernel(
    const float* __restrict__ qkv, float* __restrict__ o)
{
    extern __shared__ unsigned sm[];
    unsigned* Qs = sm;
    unsigned* Ks = sm + OFF_K;
    unsigned* Vs = sm + OFF_V;
    unsigned* Ps = sm + OFF_P;

    const int tid = threadIdx.x;
    const int w = tid >> 5;
    const int lane = tid & 31;
    const int g = lane >> 2;
    const int q = lane & 3;
    const int q0 = blockIdx.x * 128;
    const int bh = blockIdx.y;
    const int b = bh >> 4;
    const int h = bh & 15;

    const float* base = qkv + (size_t)b * S_ * 3 * D_ + h * HD_;

    // load Q tile (pre-scaled by QFOLD in rmsnorm), convert tf32
#pragma unroll
    for (int i = 0; i < 16; ++i) {
        int idx = tid + 128 * i;
        int r = idx >> 4, c = idx & 15;
        float4 v4 = *(const float4*)(base + (size_t)(q0 + r) * (3 * D_) + c * 4);
        uint4 t = make_uint4(f2tf(v4.x), f2tf(v4.y), f2tf(v4.z), f2tf(v4.w));
        *(uint4*)&Qs[r * QS_STR + c * 4] = t;
    }

    float mstate[2][2], lstate[2][2], acco[2][8][4];
#pragma unroll
    for (int mf = 0; mf < 2; ++mf)
#pragma unroll
        for (int rh = 0; rh < 2; ++rh) { mstate[mf][rh] = -1e30f; lstate[mf][rh] = 0.f; }
#pragma unroll
    for (int mf = 0; mf < 2; ++mf)
#pragma unroll
        for (int nf = 0; nf < 8; ++nf)
#pragma unroll
            for (int e = 0; e < 4; ++e) acco[mf][nf][e] = 0.f;

    for (int kv0 = 0; kv0 < S_; kv0 += 64) {
        // load K,V tiles
        float4 kb4[8], vb4[8];
#pragma unroll
        for (int i = 0; i < 8; ++i) {
            int idx = tid + 128 * i;
            int r = idx >> 4, c = idx & 15;
            const float* grow = base + (size_t)(kv0 + r) * (3 * D_);
            kb4[i] = *(const float4*)(grow + D_ + c * 4);
            vb4[i] = *(const float4*)(grow + 2 * D_ + c * 4);
        }
        __syncthreads();   // previous tile fully consumed
#pragma unroll
        for (int i = 0; i < 8; ++i) {
            int idx = tid + 128 * i;
            int r = idx >> 4, c = idx & 15;
            uint4 tk = make_uint4(f2tf(kb4[i].x), f2tf(kb4[i].y), f2tf(kb4[i].z), f2tf(kb4[i].w));
            *(uint4*)&Ks[r * KS_STR + c * 4] = tk;
            uint4 tv = make_uint4(f2tf(vb4[i].x), f2tf(vb4[i].y), f2tf(vb4[i].z), f2tf(vb4[i].w));
            *(uint4*)&Vs[r * VS_STR + c * 4] = tv;
        }
        __syncthreads();

        // S = Q K^T  (128x64, warp does 32x64)
        float accs[2][8][4];
#pragma unroll
        for (int mf = 0; mf < 2; ++mf)
#pragma unroll
            for (int nf = 0; nf < 8; ++nf)
#pragma unroll
                for (int e = 0; e < 4; ++e) accs[mf][nf][e] = 0.f;

#pragma unroll
        for (int ks = 0; ks < 8; ++ks) {
            unsigned a[2][4], bfr[8][2];
#pragma unroll
            for (int mf = 0; mf < 2; ++mf) {
                int ab = (w * 32 + mf * 16 + g) * QS_STR + ks * 8 + q;
                a[mf][0] = Qs[ab];
                a[mf][1] = Qs[ab + 8 * QS_STR];
                a[mf][2] = Qs[ab + 4];
                a[mf][3] = Qs[ab + 8 * QS_STR + 4];
            }
#pragma unroll
            for (int nf = 0; nf < 8; ++nf) {
                int kb = (nf * 8 + g) * KS_STR + ks * 8 + q;
                bfr[nf][0] = Ks[kb];
                bfr[nf][1] = Ks[kb + 4];
            }
#pragma unroll
            for (int mf = 0; mf < 2; ++mf)
#pragma unroll
                for (int nf = 0; nf < 8; ++nf)
                    mma_tf32(accs[mf][nf], a[mf], bfr[nf]);
        }

        // online softmax per row (rows live in one quad)
#pragma unroll
        for (int mf = 0; mf < 2; ++mf) {
#pragma unroll
            for (int rh = 0; rh < 2; ++rh) {
                const int e0 = rh * 2, e1 = e0 + 1;
                float mold = mstate[mf][rh];
                float mx = mold;
#pragma unroll
                for (int nf = 0; nf < 8; ++nf)
                    mx = fmaxf(mx, fmaxf(accs[mf][nf][e0], accs[mf][nf][e1]));
                mx = fmaxf(mx, __shfl_xor_sync(0xffffffffu, mx, 1));
                mx = fmaxf(mx, __shfl_xor_sync(0xffffffffu, mx, 2));
                float corr = exp2f(mold - mx);
                mstate[mf][rh] = mx;
                float sum = 0.f;
                int rowb = (w * 32 + mf * 16 + g + rh * 8) * PS_STR + 2 * q;
#pragma unroll
                for (int nf = 0; nf < 8; ++nf) {
                    float p0 = exp2f(accs[mf][nf][e0] - mx);
                    float p1 = exp2f(accs[mf][nf][e1] - mx);
                    sum += p0 + p1;
                    Ps[rowb + nf * 8] = f2tf(p0);
                    Ps[rowb + nf * 8 + 1] = f2tf(p1);
                    acco[mf][nf][e0] *= corr;
                    acco[mf][nf][e1] *= corr;
                }
                sum += __shfl_xor_sync(0xffffffffu, sum, 1);
                sum += __shfl_xor_sync(0xffffffffu, sum, 2);
                lstate[mf][rh] = lstate[mf][rh] * corr + sum;
            }
        }
        __syncwarp();   // P region is warp-private: no CTA sync needed

        // O += P V  (warp 32x64 over hd, k = 64 keys)
#pragma unroll
        for (int ks = 0; ks < 8; ++ks) {
            unsigned a[2][4], bfr[8][2];
#pragma unroll
            for (int mf = 0; mf < 2; ++mf) {
                int ab = (w * 32 + mf * 16 + g) * PS_STR + ks * 8 + q;
                a[mf][0] = Ps[ab];
                a[mf][1] = Ps[ab + 8 * PS_STR];
                a[mf][2] = Ps[ab + 4];
                a[mf][3] = Ps[ab + 8 * PS_STR + 4];
            }
#pragma unroll
            for (int nf = 0; nf < 8; ++nf) {
                int vb = (ks * 8 + q) * VS_STR + nf * 8 + g;
                bfr[nf][0] = Vs[vb];
                bfr[nf][1] = Vs[vb + 4 * VS_STR];
            }
#pragma unroll
            for (int mf = 0; mf < 2; ++mf)
#pragma unroll
                for (int nf = 0; nf < 8; ++nf)
                    mma_tf32(acco[mf][nf], a[mf], bfr[nf]);
        }
    }

    // epilogue: normalize, store
#pragma unroll
    for (int mf = 0; mf < 2; ++mf) {
#pragma unroll
        for (int rh = 0; rh < 2; ++rh) {
            float inv = 1.0f / lstate[mf][rh];
            int row = q0 + w * 32 + mf * 16 + g + rh * 8;
            float* orow = o + (size_t)(b * S_ + row) * D_ + h * HD_;
            const int e0 = rh * 2, e1 = e0 + 1;
#pragma unroll
            for (int nf = 0; nf < 8; ++nf) {
                int col = nf * 8 + 2 * q;
                *(float2*)(orow + col) =
                    make_float2(acco[mf][nf][e0] * inv, acco[mf][nf][e1] * inv);
            }
        }
    }
}

// ---------------------------------------------------------------------------
extern "C" void kernel_launch(void* const* d_in, const int* in_sizes, int n_in,
                              void* d_out, int out_size)
{
    const float* x       = (const float*)d_in[0];
    const float* Wqkv    = (const float*)d_in[1];
    const float* bqkv    = (const float*)d_in[2];
    const float* Wout    = (const float*)d_in[3];
    const float* bout    = (const float*)d_in[4];
    const float* q_scale = (const float*)d_in[5];
    const float* k_scale = (const float*)d_in[6];
    float* out = (float*)d_out;

    float* qkv; cudaGetSymbolAddress((void**)&qkv, g_qkv);
    float* o;   cudaGetSymbolAddress((void**)&o,   g_o);

    // 1) QKV projection
    {
        dim3 grid(3 * D_ / 128, (B_ * S_) / 128);
        gemm_tf32_kernel<<<grid, 256>>>(x, Wqkv, bqkv, qkv, B_ * S_, 3 * D_, D_);
    }

    // 2) RMSNorm q,k in place (q pre-scaled by QFOLD)
    {
        int warps = B_ * S_ * H_ * 2;
        rmsnorm_kernel<<<(warps * 32) / 256, 256>>>(qkv, q_scale, k_scale);
    }

    // 3) attention
    {
        cudaFuncSetAttribute((const void*)attn_tf32_kernel,
                             cudaFuncAttributeMaxDynamicSharedMemorySize, ATT_SMEM);
        dim3 grid(S_ / 128, B_ * H_);
        attn_tf32_kernel<<<grid, 128, ATT_SMEM>>>(qkv, o);
    }

    // 4) output projection
    {
        dim3 grid(D_ / 128, (B_ * S_) / 128);
        gemm_tf32_kernel<<<grid, 256>>>(o, Wout, bout, out, B_ * S_, D_, D_);
    }
}

// round 3
// speedup vs baseline: 4.1740x; 1.0142x over previous
#include <cuda_runtime.h>
#include <math.h>

#define B_  2
#define S_  2048
#define D_  1024
#define H_  16
#define HD_ 64
#define EPS_ 1e-6f
// (1/sqrt(hd)) * log2(e), folded into q rows during fused rmsnorm
#define QFOLD 0.18033688011112042f

__device__ float g_qkv[B_ * S_ * 3 * D_];   // [B*S, 3D]
__device__ float g_o[B_ * S_ * D_];         // [B*S, D]

__device__ __forceinline__ unsigned f2tf(float x) {
    unsigned r;
    asm("cvt.rna.tf32.f32 %0, %1;" : "=r"(r) : "f"(x));
    return r;
}
__device__ __forceinline__ uint4 cvt4(float4 v) {
    return make_uint4(f2tf(v.x), f2tf(v.y), f2tf(v.z), f2tf(v.w));
}
__device__ __forceinline__ void mma_tf32(float* c, const unsigned* a, const unsigned* b) {
    asm volatile(
        "mma.sync.aligned.m16n8k8.row.col.f32.tf32.tf32.f32 "
        "{%0,%1,%2,%3}, {%4,%5,%6,%7}, {%8,%9}, {%0,%1,%2,%3};"
        : "+f"(c[0]), "+f"(c[1]), "+f"(c[2]), "+f"(c[3])
        : "r"(a[0]), "r"(a[1]), "r"(a[2]), "r"(a[3]), "r"(b[0]), "r"(b[1]));
}
__device__ __forceinline__ void ldsm4(unsigned& r0, unsigned& r1, unsigned& r2,
                                      unsigned& r3, unsigned addr) {
    asm volatile("ldmatrix.sync.aligned.m8n8.x4.shared.b16 {%0,%1,%2,%3}, [%4];"
        : "=r"(r0), "=r"(r1), "=r"(r2), "=r"(r3) : "r"(addr));
}
__device__ __forceinline__ unsigned sptr(const void* p) {
    return (unsigned)__cvta_generic_to_shared(p);
}

// ---------------------------------------------------------------------------
// TF32 GEMM + bias (+optional fused per-head RMSNorm for QKV output).
// C[M,N] = A[M,K] @ B[K,N] + bias ; 128x128x32 tile, 8 warps, warp 32x64.
// As: [m][k] stride 36 ; Bt: [n][k] stride 36 (both LDSM-friendly).
// ---------------------------------------------------------------------------
#define AS_STR 36
#define BT_STR 36

__global__ __launch_bounds__(256, 2) void gemm_tf32_kernel(
    const float* __restrict__ A, const float* __restrict__ Bm,
    const float* __restrict__ bias, float* __restrict__ C,
    int M, int N, int K, int mode,
    const float* __restrict__ q_scale, const float* __restrict__ k_scale)
{
    __shared__ unsigned As[128 * AS_STR];
    __shared__ unsigned Bt[128 * BT_STR];

    const int tid = threadIdx.x;
    const int lane = tid & 31;
    const int wid = tid >> 5;
    const int g = lane >> 2;
    const int q = lane & 3;
    const int wm = wid >> 1;
    const int wn = wid & 1;
    const int bxn = blockIdx.x * 128;
    const int bym = blockIdx.y * 128;

    // A global mapping: 4 x (row, float4-col)
    int ar[4], ac[4];
    const float* Ag[4];
#pragma unroll
    for (int i = 0; i < 4; ++i) {
        int idx = tid + 256 * i;
        ar[i] = idx >> 3; ac[i] = idx & 7;
        Ag[i] = A + (size_t)(bym + ar[i]) * K + ac[i] * 4;
    }
    // B global mapping: column bn, k-halfblock kb; 16 coalesced scalar loads
    const int bn = (tid & 31) + ((tid >> 6) << 5);
    const int kb = ((tid >> 5) & 1) * 16;
    const float* Bg = Bm + bxn + bn;

    // LDSM base addresses
    unsigned a_base = sptr(As) + (((wm * 32 + (lane & 15)) * AS_STR + (lane >> 4) * 4) << 2);
    unsigned b_base = sptr(Bt) + ((((wn * 64 + (lane & 7) + ((lane >> 4) << 3))) * BT_STR
                                   + ((lane >> 3) & 1) * 4) << 2);

    float acc[2][8][4];
#pragma unroll
    for (int mf = 0; mf < 2; ++mf)
#pragma unroll
        for (int nf = 0; nf < 8; ++nf)
#pragma unroll
            for (int e = 0; e < 4; ++e) acc[mf][nf][e] = 0.f;

    const int KT = K >> 5;
    for (int kt = 0; kt < KT; ++kt) {
        const int k0 = kt * 32;
        float4 av[4];
#pragma unroll
        for (int i = 0; i < 4; ++i) av[i] = *(const float4*)(Ag[i] + k0);
        float bv[16];
#pragma unroll
        for (int r = 0; r < 4; ++r)
#pragma unroll
            for (int j = 0; j < 4; ++j)
                bv[r * 4 + j] = Bg[(size_t)(k0 + kb + r * 4 + j) * N];
        __syncthreads();
#pragma unroll
        for (int i = 0; i < 4; ++i)
            *(uint4*)&As[ar[i] * AS_STR + ac[i] * 4] = cvt4(av[i]);
#pragma unroll
        for (int r = 0; r < 4; ++r) {
            uint4 t = make_uint4(f2tf(bv[r * 4]), f2tf(bv[r * 4 + 1]),
                                 f2tf(bv[r * 4 + 2]), f2tf(bv[r * 4 + 3]));
            *(uint4*)&Bt[bn * BT_STR + kb + r * 4] = t;
        }
        __syncthreads();

#pragma unroll
        for (int kk = 0; kk < 4; ++kk) {
            unsigned a0[4], a1[4], bl[4][4];
            ldsm4(a0[0], a0[1], a0[2], a0[3], a_base + kk * 32);
            ldsm4(a1[0], a1[1], a1[2], a1[3], a_base + 16 * AS_STR * 4 + kk * 32);
#pragma unroll
            for (int t2 = 0; t2 < 4; ++t2)
                ldsm4(bl[t2][0], bl[t2][1], bl[t2][2], bl[t2][3],
                      b_base + t2 * 16 * BT_STR * 4 + kk * 32);
#pragma unroll
            for (int nf = 0; nf < 8; ++nf) {
                const unsigned* bf = &bl[nf >> 1][(nf & 1) * 2];
                mma_tf32(acc[0][nf], a0, bf);
                mma_tf32(acc[1][nf], a1, bf);
            }
        }
    }

    // epilogue: bias (+optional fused per-head rmsnorm), store
    const bool donorm = (mode == 1) && (bxn < 2048);
    const float* sc = (bxn < 1024) ? q_scale : k_scale;
    const float fold = (bxn < 1024) ? QFOLD : 1.0f;

#pragma unroll
    for (int mf = 0; mf < 2; ++mf) {
        int r0 = bym + wm * 32 + mf * 16 + g;
#pragma unroll
        for (int nf = 0; nf < 8; ++nf) {
            int col = bxn + wn * 64 + nf * 8 + 2 * q;
            float2 bs = *(const float2*)(bias + col);
            acc[mf][nf][0] += bs.x; acc[mf][nf][1] += bs.y;
            acc[mf][nf][2] += bs.x; acc[mf][nf][3] += bs.y;
        }
        if (donorm) {
#pragma unroll
            for (int rh = 0; rh < 2; ++rh) {
                const int e0 = rh * 2, e1 = e0 + 1;
                float ss = 0.f;
#pragma unroll
                for (int nf = 0; nf < 8; ++nf)
                    ss += acc[mf][nf][e0] * acc[mf][nf][e0]
                        + acc[mf][nf][e1] * acc[mf][nf][e1];
                ss += __shfl_xor_sync(0xffffffffu, ss, 1);
                ss += __shfl_xor_sync(0xffffffffu, ss, 2);
                float rr = rsqrtf(ss * (1.0f / HD_) + EPS_) * fold;
#pragma unroll
                for (int nf = 0; nf < 8; ++nf) {
                    float2 s2 = *(const float2*)(sc + nf * 8 + 2 * q);
                    acc[mf][nf][e0] *= rr * s2.x;
                    acc[mf][nf][e1] *= rr * s2.y;
                }
            }
        }
#pragma unroll
        for (int nf = 0; nf < 8; ++nf) {
            int col = bxn + wn * 64 + nf * 8 + 2 * q;
            *(float2*)(C + (size_t)r0 * N + col) =
                make_float2(acc[mf][nf][0], acc[mf][nf][1]);
            *(float2*)(C + (size_t)(r0 + 8) * N + col) =
                make_float2(acc[mf][nf][2], acc[mf][nf][3]);
        }
    }
}

// ---------------------------------------------------------------------------
// TF32 flash attention, full-LDSM. CTA: 256 thr (8 warps), 128 queries,
// warp = 16 q-rows x 64 keys. Vt stored transposed [hd][key] for LDSM.
// ---------------------------------------------------------------------------
#define TS 68
#define OFF_K  (128 * TS)
#define OFF_V  (OFF_K + 64 * TS)
#define OFF_P  (OFF_V + 64 * TS)
#define ATT_SMEM ((OFF_P + 128 * TS) * 4)

__global__ __launch_bounds__(256, 2) void attn_tf32_kernel(
    const float* __restrict__ qkv, float* __restrict__ o)
{
    extern __shared__ unsigned sm[];
    unsigned* Qs = sm;
    unsigned* Ks = sm + OFF_K;
    unsigned* Vt = sm + OFF_V;
    unsigned* Ps = sm + OFF_P;

    const int tid = threadIdx.x;
    const int lane = tid & 31;
    const int w = tid >> 5;
    const int g = lane >> 2;
    const int q = lane & 3;
    const int q0 = blockIdx.x * 128;
    const int bh = blockIdx.y;
    const int b = bh >> 4;
    const int h = bh & 15;

    const float* base = qkv + (size_t)b * S_ * 3 * D_ + h * HD_;

    // load Q tile (QFOLD pre-applied in gemm epilogue)
#pragma unroll
    for (int i = 0; i < 8; ++i) {
        int idx = tid + 256 * i;
        int r = idx >> 4, c = idx & 15;
        float4 v4 = *(const float4*)(base + (size_t)(q0 + r) * (3 * D_) + c * 4);
        *(uint4*)&Qs[r * TS + c * 4] = cvt4(v4);
    }

    // V load mapping: per thread hd column, 16 keys
    const int vhd = (tid & 31) + ((tid >> 5) & 1) * 32;
    const int vk0 = (tid >> 6) * 16;

    // LDSM bases
    unsigned qbase = sptr(Qs) + (((w * 16 + (lane & 15)) * TS + (lane >> 4) * 4) << 2);
    unsigned pbase = sptr(Ps) + (((w * 16 + (lane & 15)) * TS + (lane >> 4) * 4) << 2);
    const unsigned brow = (((lane & 7) + ((lane >> 4) << 3)) * TS + ((lane >> 3) & 1) * 4) << 2;
    unsigned kbase = sptr(Ks) + brow;
    unsigned vbase = sptr(Vt) + brow;

    float mst[2] = {-1e30f, -1e30f}, lst[2] = {0.f, 0.f};
    float acco[8][4];
#pragma unroll
    for (int nf = 0; nf < 8; ++nf)
#pragma unroll
        for (int e = 0; e < 4; ++e) acco[nf][e] = 0.f;

    for (int kv0 = 0; kv0 < S_; kv0 += 64) {
        // K: 4 coalesced float4 per thread
        float4 kv4[4];
#pragma unroll
        for (int i = 0; i < 4; ++i) {
            int idx = tid + 256 * i;
            int r = idx >> 4, c = idx & 15;
            kv4[i] = *(const float4*)(base + (size_t)(kv0 + r) * (3 * D_) + D_ + c * 4);
        }
        // V: 16 coalesced scalars (one hd column, 16 keys)
        float vv[16];
        const float* vp = base + (size_t)(kv0 + vk0) * (3 * D_) + 2 * D_ + vhd;
#pragma unroll
        for (int j = 0; j < 16; ++j) vv[j] = vp[(size_t)j * (3 * D_)];

        __syncthreads();   // prior tile fully consumed
#pragma unroll
        for (int i = 0; i < 4; ++i) {
            int idx = tid + 256 * i;
            int r = idx >> 4, c = idx & 15;
            *(uint4*)&Ks[r * TS + c * 4] = cvt4(kv4[i]);
        }
#pragma unroll
        for (int rep = 0; rep < 4; ++rep) {
            uint4 t = make_uint4(f2tf(vv[rep * 4]), f2tf(vv[rep * 4 + 1]),
                                 f2tf(vv[rep * 4 + 2]), f2tf(vv[rep * 4 + 3]));
            *(uint4*)&Vt[vhd * TS + vk0 + rep * 4] = t;
        }
        __syncthreads();

        // S = Q K^T
        float accs[8][4];
#pragma unroll
        for (int nf = 0; nf < 8; ++nf)
#pragma unroll
            for (int e = 0; e < 4; ++e) accs[nf][e] = 0.f;
#pragma unroll
        for (int ks = 0; ks < 8; ++ks) {
            unsigned a[4], bl[4][4];
            ldsm4(a[0], a[1], a[2], a[3], qbase + ks * 32);
#pragma unroll
            for (int t2 = 0; t2 < 4; ++t2)
                ldsm4(bl[t2][0], bl[t2][1], bl[t2][2], bl[t2][3],
                      kbase + t2 * 16 * TS * 4 + ks * 32);
#pragma unroll
            for (int nf = 0; nf < 8; ++nf)
                mma_tf32(accs[nf], a, &bl[nf >> 1][(nf & 1) * 2]);
        }

        // online softmax (rows in quads)
#pragma unroll
        for (int rh = 0; rh < 2; ++rh) {
            const int e0 = rh * 2, e1 = e0 + 1;
            float mold = mst[rh];
            float mx = mold;
#pragma unroll
            for (int nf = 0; nf < 8; ++nf)
                mx = fmaxf(mx, fmaxf(accs[nf][e0], accs[nf][e1]));
            mx = fmaxf(mx, __shfl_xor_sync(0xffffffffu, mx, 1));
            mx = fmaxf(mx, __shfl_xor_sync(0xffffffffu, mx, 2));
            float corr = exp2f(mold - mx);
            mst[rh] = mx;
            float sum = 0.f;
            int rowb = (w * 16 + g + rh * 8) * TS + 2 * q;
#pragma unroll
            for (int nf = 0; nf < 8; ++nf) {
                float p0 = exp2f(accs[nf][e0] - mx);
                float p1 = exp2f(accs[nf][e1] - mx);
                sum += p0 + p1;
                Ps[rowb + nf * 8] = f2tf(p0);
                Ps[rowb + nf * 8 + 1] = f2tf(p1);
                acco[nf][e0] *= corr;
                acco[nf][e1] *= corr;
            }
            sum += __shfl_xor_sync(0xffffffffu, sum, 1);
            sum += __shfl_xor_sync(0xffffffffu, sum, 2);
            lst[rh] = lst[rh] * corr + sum;
        }
        __syncwarp();   // P is warp-private

        // O += P V
#pragma unroll
        for (int ks = 0; ks < 8; ++ks) {
            unsigned a[4], bl[4][4];
            ldsm4(a[0], a[1], a[2], a[3], pbase + ks * 32);
#pragma unroll
            for (int t2 = 0; t2 < 4; ++t2)
                ldsm4(bl[t2][0], bl[t2][1], bl[t2][2], bl[t2][3],
                      vbase + t2 * 16 * TS * 4 + ks * 32);
#pragma unroll
            for (int nf = 0; nf < 8; ++nf)
                mma_tf32(acco[nf], a, &bl[nf >> 1][(nf & 1) * 2]);
        }
    }

    // epilogue: normalize, store
#pragma unroll
    for (int rh = 0; rh < 2; ++rh) {
        float inv = 1.0f / lst[rh];
        int row = q0 + w * 16 + g + rh * 8;
        float* orow = o + (size_t)(b * S_ + row) * D_ + h * HD_;
        const int e0 = rh * 2, e1 = e0 + 1;
#pragma unroll
        for (int nf = 0; nf < 8; ++nf)
            *(float2*)(orow + nf * 8 + 2 * q) =
                make_float2(acco[nf][e0] * inv, acco[nf][e1] * inv);
    }
}

// ---------------------------------------------------------------------------
extern "C" void kernel_launch(void* const* d_in, const int* in_sizes, int n_in,
                              void* d_out, int out_size)
{
    const float* x       = (const float*)d_in[0];
    const float* Wqkv    = (const float*)d_in[1];
    const float* bqkv    = (const float*)d_in[2];
    const float* Wout    = (const float*)d_in[3];
    const float* bout    = (const float*)d_in[4];
    const float* q_scale = (const float*)d_in[5];
    const float* k_scale = (const float*)d_in[6];
    float* out = (float*)d_out;

    float* qkv; cudaGetSymbolAddress((void**)&qkv, g_qkv);
    float* o;   cudaGetSymbolAddress((void**)&o,   g_o);

    // 1) QKV projection with fused per-head RMSNorm on q,k
    {
        dim3 grid(3 * D_ / 128, (B_ * S_) / 128);
        gemm_tf32_kernel<<<grid, 256>>>(x, Wqkv, bqkv, qkv, B_ * S_, 3 * D_, D_,
                                        1, q_scale, k_scale);
    }
    // 2) attention
    {
        cudaFuncSetAttribute((const void*)attn_tf32_kernel,
                             cudaFuncAttributeMaxDynamicSharedMemorySize, ATT_SMEM);
        dim3 grid(S_ / 128, B_ * H_);
        attn_tf32_kernel<<<grid, 256, ATT_SMEM>>>(qkv, o);
    }
    // 3) output projection
    {
        dim3 grid(D_ / 128, (B_ * S_) / 128);
        gemm_tf32_kernel<<<grid, 256>>>(o, Wout, bout, out, B_ * S_, D_, D_,
                                        0, q_scale, k_scale);
    }
}